// round 3
// baseline (speedup 1.0000x reference)
#include <cuda_runtime.h>
#include <cuda_fp16.h>
#include <cstdint>

#define N_C    16
#define DIN    1024
#define HID    128
#define TILE_M 128
#define KC     64

// ---------------- device scratch ----------------
__device__ __align__(1024) __half g_xh [67108864];        // 65536*1024 fp16
__device__ __align__(1024) __half g_w1t[N_C * HID * DIN]; // [c][h][d] K-major
__device__ __align__(1024) __half g_w2t[N_C * HID * HID]; // [c][ho][hi] K-major

// ---------------- smem layout ----------------
#define OFF_SA(s)    ((uint32_t)(s) * 16384u)                          // 0, 16384
#define OFF_SB(s,ch) (32768u + ((uint32_t)(s) * 2u + (uint32_t)(ch)) * 16384u)
#define OFF_SBI(i)   (32768u + (uint32_t)(i) * 16384u)                 // 4 slots
#define OFF_H1(ch)   (98304u + (uint32_t)(ch) * 32768u)                // 2 x 32KB
#define OFF_B1S 163840u
#define OFF_B2S 164864u
#define OFF_W3S 165888u
#define OFF_ACC 166912u
#define SMEM_TOTAL 167936u

#define SWZ(bo) ((bo) ^ (((bo) >> 3) & 0x70))

__device__ __forceinline__ uint32_t smem_u32(const void* p) {
    uint32_t a;
    asm("{ .reg .u64 t; cvta.to.shared.u64 t, %1; cvt.u32.u64 %0, t; }" : "=r"(a) : "l"(p));
    return a;
}

// cp.async a [128 x 128B] tile into swizzled smem; 256 threads, 16B each, 4 iters
__device__ __forceinline__ void cpa_tile(uint32_t soff_abs, const char* g,
                                         int stride_bytes, int tid) {
#pragma unroll
    for (int it = 0; it < 4; ++it) {
        int u = it * 256 + tid;
        int r = u >> 3, w = u & 7;
        uint32_t d = soff_abs + SWZ((uint32_t)(r * 128 + w * 16));
        const char* src = g + (size_t)r * stride_bytes + w * 16;
        asm volatile("cp.async.cg.shared.global [%0], [%1], 16;" :: "r"(d), "l"(src));
    }
}
#define CPA_COMMIT() asm volatile("cp.async.commit_group;" ::: "memory")
#define CPA_WAIT0()  asm volatile("cp.async.wait_group 0;" ::: "memory")
#define CPA_WAIT1()  asm volatile("cp.async.wait_group 1;" ::: "memory")

__device__ __forceinline__ void ldmA(uint32_t addr, uint32_t* f) {
    asm volatile("ldmatrix.sync.aligned.m8n8.x4.shared.b16 {%0,%1,%2,%3}, [%4];"
                 : "=r"(f[0]), "=r"(f[1]), "=r"(f[2]), "=r"(f[3]) : "r"(addr));
}
// x4 B load: fetches b[nt=2q][k0], b[2q][k1], b[2q+1][k0], b[2q+1][k1]
__device__ __forceinline__ void ldmB4(uint32_t addr, uint32_t* f) {
    asm volatile("ldmatrix.sync.aligned.m8n8.x4.shared.b16 {%0,%1,%2,%3}, [%4];"
                 : "=r"(f[0]), "=r"(f[1]), "=r"(f[2]), "=r"(f[3]) : "r"(addr));
}
__device__ __forceinline__ void mma16816(float* c, const uint32_t* a, const uint32_t* b) {
    asm volatile(
        "mma.sync.aligned.m16n8k16.row.col.f32.f16.f16.f32 "
        "{%0,%1,%2,%3}, {%4,%5,%6,%7}, {%8,%9}, {%0,%1,%2,%3};"
        : "+f"(c[0]), "+f"(c[1]), "+f"(c[2]), "+f"(c[3])
        : "r"(a[0]), "r"(a[1]), "r"(a[2]), "r"(a[3]), "r"(b[0]), "r"(b[1]));
}

// B-fragment addresses for ldmB4, pair q (covers nt=2q, 2q+1)
__device__ __forceinline__ uint32_t b4_addr(uint32_t sB, int ks, int q, int lane, int wn) {
    int grp = lane >> 3;
    int row = wn * 32 + (2 * q + (grp >> 1)) * 8 + (lane & 7);
    uint32_t bo = (uint32_t)(row * 128 + ks * 32 + ((grp & 1) << 4));
    return sB + SWZ(bo);
}

// single-channel 64-wide K chunk (used by GEMM2)
__device__ __forceinline__ void gemm64(uint32_t sA, uint32_t sB,
                                       float acc[4][4][4], int lane, int wm, int wn) {
#pragma unroll
    for (int ks = 0; ks < 4; ++ks) {
        uint32_t a[4][4], b[4][2];
#pragma unroll
        for (int mt = 0; mt < 4; ++mt) {
            int row = wm * 64 + mt * 16 + (lane & 15);
            uint32_t bo = (uint32_t)(row * 128 + ks * 32 + ((lane >> 4) << 4));
            ldmA(sA + SWZ(bo), a[mt]);
        }
#pragma unroll
        for (int q = 0; q < 2; ++q)
            ldmB4(b4_addr(sB, ks, q, lane, wn), &b[2 * q][0]);
#pragma unroll
        for (int mt = 0; mt < 4; ++mt)
#pragma unroll
            for (int nt = 0; nt < 4; ++nt)
                mma16816(acc[mt][nt], a[mt], b[nt]);
    }
}

// two-channel chunk: one A tile, two B tiles (GEMM1)
__device__ __forceinline__ void gemm64_2ch(uint32_t sA, uint32_t sB0, uint32_t sB1,
                                           float acc[2][4][4][4], int lane, int wm, int wn) {
#pragma unroll
    for (int ks = 0; ks < 4; ++ks) {
        uint32_t a[4][4], b0[4][2], b1f[4][2];
#pragma unroll
        for (int mt = 0; mt < 4; ++mt) {
            int row = wm * 64 + mt * 16 + (lane & 15);
            uint32_t bo = (uint32_t)(row * 128 + ks * 32 + ((lane >> 4) << 4));
            ldmA(sA + SWZ(bo), a[mt]);
        }
#pragma unroll
        for (int q = 0; q < 2; ++q) {
            ldmB4(b4_addr(sB0, ks, q, lane, wn), &b0[2 * q][0]);
            ldmB4(b4_addr(sB1, ks, q, lane, wn), &b1f[2 * q][0]);
        }
#pragma unroll
        for (int mt = 0; mt < 4; ++mt)
#pragma unroll
            for (int nt = 0; nt < 4; ++nt) {
                mma16816(acc[0][mt][nt], a[mt], b0[nt]);
                mma16816(acc[1][mt][nt], a[mt], b1f[nt]);
            }
    }
}

// ---------------- merged prep kernel ----------------
__global__ void prep_all(const float* __restrict__ x, const float* __restrict__ W1,
                         const float* __restrict__ W2, int xblocks) {
    if ((int)blockIdx.x < xblocks) {
        int i = blockIdx.x * 256 + threadIdx.x;
        float4 v = ((const float4*)x)[i];
        __half2* o = (__half2*)g_xh;
        o[2 * i]     = __floats2half2_rn(v.x, v.y);
        o[2 * i + 1] = __floats2half2_rn(v.z, v.w);
    } else {
        int i = (blockIdx.x - xblocks) * 256 + threadIdx.x;
        const int n1 = N_C * DIN * HID;
        if (i < n1) {
            int c = i / (DIN * HID);
            int rem = i % (DIN * HID);
            int h = rem / DIN;
            int d = rem % DIN;
            g_w1t[i] = __float2half_rn(W1[(c * DIN + d) * HID + h]);
        } else {
            int k = i - n1;
            if (k < N_C * HID * HID) {
                int c = k / (HID * HID);
                int rem = k % (HID * HID);
                int ho = rem / HID;
                int hi = rem % HID;
                g_w2t[k] = __float2half_rn(W2[(c * HID + hi) * HID + ho]);
            }
        }
    }
}

// ---------------- main fused MLP kernel ----------------
__global__ void __launch_bounds__(256, 1) mlp_main(
    const float* __restrict__ b1, const float* __restrict__ b2,
    const float* __restrict__ W3, const float* __restrict__ b3,
    float* __restrict__ out) {
    extern __shared__ char smem[];
    const uint32_t sbase = smem_u32(smem);
    const int tid  = threadIdx.x;
    const int lane = tid & 31;
    const int wid  = tid >> 5;
    const int wm   = wid >> 2;
    const int wn   = wid & 3;
    const int row0 = blockIdx.x * TILE_M;

    float* b1s    = (float*)(smem + OFF_B1S);   // [2][128]
    float* b2s    = (float*)(smem + OFF_B2S);
    float* w3s    = (float*)(smem + OFF_W3S);
    float* rowacc = (float*)(smem + OFF_ACC);   // [2][128]

    float acc[2][4][4][4];
    const char* xg = (const char*)(g_xh + (size_t)row0 * DIN);

    // prologue: x chunk0 + pair0 B chunk0
    cpa_tile(sbase + OFF_SA(0), xg, DIN * 2, tid);
    cpa_tile(sbase + OFF_SB(0, 0), (const char*)g_w1t, DIN * 2, tid);
    cpa_tile(sbase + OFF_SB(0, 1), (const char*)(g_w1t + (size_t)HID * DIN), DIN * 2, tid);
    CPA_COMMIT();

#pragma unroll 1
    for (int p = 0; p < N_C / 2; ++p) {
        const int c0 = 2 * p;
        {
            int ch = tid >> 7, h = tid & 127;
            b1s[tid] = b1[(c0 + ch) * HID + h];
            b2s[tid] = b2[(c0 + ch) * HID + h];
            w3s[tid] = W3[(c0 + ch) * HID + h];
            rowacc[tid] = 0.f;
        }
#pragma unroll
        for (int ch = 0; ch < 2; ++ch)
#pragma unroll
            for (int mt = 0; mt < 4; ++mt)
#pragma unroll
                for (int nt = 0; nt < 4; ++nt)
#pragma unroll
                    for (int i = 0; i < 4; ++i) acc[ch][mt][nt][i] = 0.f;

        const char* w1a = (const char*)(g_w1t + (size_t)c0 * HID * DIN);
        const char* w1b = (const char*)(g_w1t + (size_t)(c0 + 1) * HID * DIN);

        // ================= GEMM1 (both channels) =================
#pragma unroll 1
        for (int j = 0; j < DIN / KC; ++j) {
            if (j < DIN / KC - 1) {
                int nb = (j + 1) & 1;
                cpa_tile(sbase + OFF_SA(nb), xg + (size_t)(j + 1) * KC * 2, DIN * 2, tid);
                cpa_tile(sbase + OFF_SB(nb, 0), w1a + (size_t)(j + 1) * KC * 2, DIN * 2, tid);
                cpa_tile(sbase + OFF_SB(nb, 1), w1b + (size_t)(j + 1) * KC * 2, DIN * 2, tid);
                CPA_COMMIT();
                CPA_WAIT1();
            } else {
                CPA_WAIT0();
            }
            __syncthreads();
            int bsel = j & 1;
            gemm64_2ch(sbase + OFF_SA(bsel), sbase + OFF_SB(bsel, 0),
                       sbase + OFF_SB(bsel, 1), acc, lane, wm, wn);
            __syncthreads();
        }

        // W2 loads (+ next-pair x chunk0 refill) overlap epilogue 1
        const char* w2a = (const char*)(g_w2t + (size_t)c0 * HID * HID);
        const char* w2b = (const char*)(g_w2t + (size_t)(c0 + 1) * HID * HID);
        cpa_tile(sbase + OFF_SBI(0), w2a, HID * 2, tid);
        cpa_tile(sbase + OFF_SBI(1), w2a + (size_t)KC * 2, HID * 2, tid);
        cpa_tile(sbase + OFF_SBI(2), w2b, HID * 2, tid);
        cpa_tile(sbase + OFF_SBI(3), w2b + (size_t)KC * 2, HID * 2, tid);
        if (p < N_C / 2 - 1) cpa_tile(sbase + OFF_SA(0), xg, DIN * 2, tid);
        CPA_COMMIT();

        // ============ epilogue 1: relu(acc + b1) -> fp16 h1 smem ============
#pragma unroll
        for (int ch = 0; ch < 2; ++ch) {
#pragma unroll
            for (int mt = 0; mt < 4; ++mt) {
                int r1 = wm * 64 + mt * 16 + (lane >> 2);
#pragma unroll
                for (int nt = 0; nt < 4; ++nt) {
                    int n = wn * 32 + nt * 8 + (lane & 3) * 2;
                    uint32_t chb = OFF_H1(ch) + (uint32_t)(n >> 6) * 16384u;
                    uint32_t nc = (uint32_t)(n & 63);
                    float* cc = acc[ch][mt][nt];
                    float bb0 = b1s[ch * 128 + n], bb1 = b1s[ch * 128 + n + 1];
                    __half2 h0 = __floats2half2_rn(fmaxf(cc[0] + bb0, 0.f),
                                                   fmaxf(cc[1] + bb1, 0.f));
                    __half2 h1 = __floats2half2_rn(fmaxf(cc[2] + bb0, 0.f),
                                                   fmaxf(cc[3] + bb1, 0.f));
                    *(__half2*)(smem + chb + SWZ((uint32_t)r1 * 128u + nc * 2u)) = h0;
                    *(__half2*)(smem + chb + SWZ((uint32_t)(r1 + 8) * 128u + nc * 2u)) = h1;
                }
            }
        }
        CPA_WAIT0();
        __syncthreads();

        // ================= GEMM2 (per channel) =================
#pragma unroll
        for (int ch = 0; ch < 2; ++ch)
#pragma unroll
            for (int mt = 0; mt < 4; ++mt)
#pragma unroll
                for (int nt = 0; nt < 4; ++nt)
#pragma unroll
                    for (int i = 0; i < 4; ++i) acc[ch][mt][nt][i] = 0.f;

        gemm64(sbase + OFF_H1(0),           sbase + OFF_SBI(0), acc[0], lane, wm, wn);
        gemm64(sbase + OFF_H1(0) + 16384u,  sbase + OFF_SBI(1), acc[0], lane, wm, wn);
        gemm64(sbase + OFF_H1(1),           sbase + OFF_SBI(2), acc[1], lane, wm, wn);
        gemm64(sbase + OFF_H1(1) + 16384u,  sbase + OFF_SBI(3), acc[1], lane, wm, wn);
        __syncthreads();

        // prefetch next pair's B chunk0 (overlaps epilogue 2)
        if (p < N_C / 2 - 1) {
            cpa_tile(sbase + OFF_SB(0, 0),
                     (const char*)(g_w1t + (size_t)(c0 + 2) * HID * DIN), DIN * 2, tid);
            cpa_tile(sbase + OFF_SB(0, 1),
                     (const char*)(g_w1t + (size_t)(c0 + 3) * HID * DIN), DIN * 2, tid);
            CPA_COMMIT();
        }

        // ============ epilogue 2: out = relu(acc + b2) . W3 + b3 ============
#pragma unroll
        for (int ch = 0; ch < 2; ++ch) {
#pragma unroll
            for (int mt = 0; mt < 4; ++mt) {
                float p1 = 0.f, p2 = 0.f;
#pragma unroll
                for (int nt = 0; nt < 4; ++nt) {
                    int n = wn * 32 + nt * 8 + (lane & 3) * 2;
                    float* cc = acc[ch][mt][nt];
                    float w0 = w3s[ch * 128 + n], w1v = w3s[ch * 128 + n + 1];
                    float c2a = b2s[ch * 128 + n], c2b = b2s[ch * 128 + n + 1];
                    p1 += fmaxf(cc[0] + c2a, 0.f) * w0 + fmaxf(cc[1] + c2b, 0.f) * w1v;
                    p2 += fmaxf(cc[2] + c2a, 0.f) * w0 + fmaxf(cc[3] + c2b, 0.f) * w1v;
                }
                p1 += __shfl_xor_sync(0xFFFFFFFFu, p1, 1);
                p1 += __shfl_xor_sync(0xFFFFFFFFu, p1, 2);
                p2 += __shfl_xor_sync(0xFFFFFFFFu, p2, 1);
                p2 += __shfl_xor_sync(0xFFFFFFFFu, p2, 2);
                if ((lane & 3) == 0) {
                    int r = wm * 64 + mt * 16 + (lane >> 2);
                    atomicAdd(&rowacc[ch * 128 + r], p1);
                    atomicAdd(&rowacc[ch * 128 + r + 8], p2);
                }
            }
        }
        __syncthreads();
        {
            int ch = tid >> 7, r = tid & 127;
            out[(size_t)(row0 + r) * N_C + c0 + ch] = rowacc[tid] + b3[c0 + ch];
        }
        __syncthreads();
    }
}

// ---------------- launch ----------------
extern "C" void kernel_launch(void* const* d_in, const int* in_sizes, int n_in,
                              void* d_out, int out_size) {
    const float* x  = (const float*)d_in[0];
    const float* W1 = (const float*)d_in[1];
    const float* b1 = (const float*)d_in[2];
    const float* W2 = (const float*)d_in[3];
    const float* b2 = (const float*)d_in[4];
    const float* W3 = (const float*)d_in[5];
    const float* b3 = (const float*)d_in[6];
    float* out = (float*)d_out;

    const int npts = in_sizes[0] / DIN;               // 65536
    const int xblocks = npts * (DIN / 4) / 256;       // 65536
    const int wtot = N_C * DIN * HID + N_C * HID * HID;
    const int wblocks = (wtot + 255) / 256;

    prep_all<<<xblocks + wblocks, 256>>>(x, W1, W2, xblocks);

    cudaFuncSetAttribute(mlp_main, cudaFuncAttributeMaxDynamicSharedMemorySize, SMEM_TOTAL);
    mlp_main<<<npts / TILE_M, 256, SMEM_TOTAL>>>(b1, b2, W3, b3, out);
}

// round 4
// speedup vs baseline: 1.0347x; 1.0347x over previous
#include <cuda_runtime.h>
#include <cuda_fp16.h>
#include <cstdint>

#define N_C    16
#define DIN    1024
#define HID    128
#define TILE_M 128
#define KC     64
#define NCHUNK (DIN / KC)   // 16

// ---------------- device scratch ----------------
__device__ __align__(1024) __half g_xh [67108864];        // 65536*1024 fp16
__device__ __align__(1024) __half g_w1t[N_C * HID * DIN]; // [c][h][d] K-major
__device__ __align__(1024) __half g_w2t[N_C * HID * HID]; // [c][ho][hi] K-major

// ---------------- smem layout: 3 ring slots of 32KB (A 16KB + B 16KB) ----------------
#define OFF_STG(s) ((uint32_t)(s) * 32768u)
#define OFF_H1     OFF_STG(0)               // 32KB: h1 chunk0 @ +0, chunk1 @ +16384
#define OFF_W2     OFF_STG(2)               // 32KB: W2 chunk0 @ +0, chunk1 @ +16384
#define OFF_B1S    98304u
#define OFF_B2S    98816u
#define OFF_W3S    99328u
#define OFF_ACC    99840u
#define SMEM_TOTAL 100352u

#define SWZ(bo) ((bo) ^ (((bo) >> 3) & 0x70))

__device__ __forceinline__ uint32_t smem_u32(const void* p) {
    uint32_t a;
    asm("{ .reg .u64 t; cvta.to.shared.u64 t, %1; cvt.u32.u64 %0, t; }" : "=r"(a) : "l"(p));
    return a;
}

// cp.async a [128 x 128B] tile into swizzled smem; 256 threads, 16B each, 4 iters
__device__ __forceinline__ void cpa_tile(uint32_t soff_abs, const char* g,
                                         int stride_bytes, int tid) {
#pragma unroll
    for (int it = 0; it < 4; ++it) {
        int u = it * 256 + tid;
        int r = u >> 3, w = u & 7;
        uint32_t d = soff_abs + SWZ((uint32_t)(r * 128 + w * 16));
        const char* src = g + (size_t)r * stride_bytes + w * 16;
        asm volatile("cp.async.cg.shared.global [%0], [%1], 16;" :: "r"(d), "l"(src));
    }
}
#define CPA_COMMIT() asm volatile("cp.async.commit_group;" ::: "memory")
#define CPA_WAIT(n)  asm volatile("cp.async.wait_group %0;" :: "n"(n) : "memory")

__device__ __forceinline__ void ldmA(uint32_t addr, uint32_t* f) {
    asm volatile("ldmatrix.sync.aligned.m8n8.x4.shared.b16 {%0,%1,%2,%3}, [%4];"
                 : "=r"(f[0]), "=r"(f[1]), "=r"(f[2]), "=r"(f[3]) : "r"(addr));
}
__device__ __forceinline__ void ldmB4(uint32_t addr, uint32_t* f) {
    asm volatile("ldmatrix.sync.aligned.m8n8.x4.shared.b16 {%0,%1,%2,%3}, [%4];"
                 : "=r"(f[0]), "=r"(f[1]), "=r"(f[2]), "=r"(f[3]) : "r"(addr));
}
__device__ __forceinline__ void mma16816(float* c, const uint32_t* a, const uint32_t* b) {
    asm volatile(
        "mma.sync.aligned.m16n8k16.row.col.f32.f16.f16.f32 "
        "{%0,%1,%2,%3}, {%4,%5,%6,%7}, {%8,%9}, {%0,%1,%2,%3};"
        : "+f"(c[0]), "+f"(c[1]), "+f"(c[2]), "+f"(c[3])
        : "r"(a[0]), "r"(a[1]), "r"(a[2]), "r"(a[3]), "r"(b[0]), "r"(b[1]));
}

__device__ __forceinline__ uint32_t b4_addr(uint32_t sB, int ks, int q, int lane, int wn) {
    int grp = lane >> 3;
    int row = wn * 32 + (2 * q + (grp >> 1)) * 8 + (lane & 7);
    uint32_t bo = (uint32_t)(row * 128 + ks * 32 + ((grp & 1) << 4));
    return sB + SWZ(bo);
}

// one 64-wide K chunk: A [128x64] at sA, B [128x64] at sB (both swizzled)
__device__ __forceinline__ void gemm64(uint32_t sA, uint32_t sB,
                                       float acc[4][4][4], int lane, int wm, int wn) {
#pragma unroll
    for (int ks = 0; ks < 4; ++ks) {
        uint32_t a[4][4], b[4][2];
#pragma unroll
        for (int mt = 0; mt < 4; ++mt) {
            int row = wm * 64 + mt * 16 + (lane & 15);
            uint32_t bo = (uint32_t)(row * 128 + ks * 32 + ((lane >> 4) << 4));
            ldmA(sA + SWZ(bo), a[mt]);
        }
#pragma unroll
        for (int q = 0; q < 2; ++q)
            ldmB4(b4_addr(sB, ks, q, lane, wn), &b[2 * q][0]);
#pragma unroll
        for (int mt = 0; mt < 4; ++mt)
#pragma unroll
            for (int nt = 0; nt < 4; ++nt)
                mma16816(acc[mt][nt], a[mt], b[nt]);
    }
}

// ---------------- merged prep kernel ----------------
__global__ void prep_all(const float* __restrict__ x, const float* __restrict__ W1,
                         const float* __restrict__ W2, int xblocks) {
    if ((int)blockIdx.x < xblocks) {
        int i = blockIdx.x * 256 + threadIdx.x;
        float4 v = ((const float4*)x)[i];
        __half2* o = (__half2*)g_xh;
        o[2 * i]     = __floats2half2_rn(v.x, v.y);
        o[2 * i + 1] = __floats2half2_rn(v.z, v.w);
    } else {
        int i = (blockIdx.x - xblocks) * 256 + threadIdx.x;
        const int n1 = N_C * DIN * HID;
        if (i < n1) {
            int c = i / (DIN * HID);
            int rem = i % (DIN * HID);
            int h = rem / DIN;
            int d = rem % DIN;
            g_w1t[i] = __float2half_rn(W1[(c * DIN + d) * HID + h]);
        } else {
            int k = i - n1;
            if (k < N_C * HID * HID) {
                int c = k / (HID * HID);
                int rem = k % (HID * HID);
                int ho = rem / HID;
                int hi = rem % HID;
                g_w2t[k] = __float2half_rn(W2[(c * HID + hi) * HID + ho]);
            }
        }
    }
}

// ---------------- main fused MLP kernel ----------------
__global__ void __launch_bounds__(256, 2) mlp_main(
    const float* __restrict__ b1, const float* __restrict__ b2,
    const float* __restrict__ W3, const float* __restrict__ b3,
    float* __restrict__ out) {
    extern __shared__ char smem[];
    const uint32_t sbase = smem_u32(smem);
    const int tid  = threadIdx.x;
    const int lane = tid & 31;
    const int wid  = tid >> 5;
    const int wm   = wid >> 2;
    const int wn   = wid & 3;
    const int row0 = blockIdx.x * TILE_M;

    float* b1s    = (float*)(smem + OFF_B1S);
    float* b2s    = (float*)(smem + OFF_B2S);
    float* w3s    = (float*)(smem + OFF_W3S);
    float* rowacc = (float*)(smem + OFF_ACC);

    float acc[4][4][4];
    const char* xg = (const char*)(g_xh + (size_t)row0 * DIN);

    // prologue: channel 0, chunks 0 and 1 into ring slots 0 and 1
    {
        const char* w1c = (const char*)g_w1t;
        cpa_tile(sbase + OFF_STG(0), xg, DIN * 2, tid);
        cpa_tile(sbase + OFF_STG(0) + 16384u, w1c, DIN * 2, tid);
        CPA_COMMIT();
        cpa_tile(sbase + OFF_STG(1), xg + (size_t)KC * 2, DIN * 2, tid);
        cpa_tile(sbase + OFF_STG(1) + 16384u, w1c + (size_t)KC * 2, DIN * 2, tid);
        CPA_COMMIT();
    }

#pragma unroll 1
    for (int c = 0; c < N_C; ++c) {
        if (tid < HID) {
            b1s[tid] = b1[c * HID + tid];
            b2s[tid] = b2[c * HID + tid];
            w3s[tid] = W3[c * HID + tid];
            rowacc[tid] = 0.f;
        }
#pragma unroll
        for (int mt = 0; mt < 4; ++mt)
#pragma unroll
            for (int nt = 0; nt < 4; ++nt)
#pragma unroll
                for (int i = 0; i < 4; ++i) acc[mt][nt][i] = 0.f;

        const char* w1c = (const char*)(g_w1t + (size_t)c * HID * DIN);

        // ========== GEMM1: 16 chunks, 3-stage ring, one sync per chunk ==========
#pragma unroll 1
        for (int j = 0; j < NCHUNK; ++j) {
            if (j < NCHUNK - 1) CPA_WAIT(1); else CPA_WAIT(0);
            __syncthreads();               // stage j visible to all; slot (j-1)%3 free
            if (j + 2 < NCHUNK) {
                int s = (j + 2) % 3;
                cpa_tile(sbase + OFF_STG(s), xg + (size_t)(j + 2) * KC * 2, DIN * 2, tid);
                cpa_tile(sbase + OFF_STG(s) + 16384u, w1c + (size_t)(j + 2) * KC * 2,
                         DIN * 2, tid);
                CPA_COMMIT();
            }
            int s = j % 3;
            gemm64(sbase + OFF_STG(s), sbase + OFF_STG(s) + 16384u, acc, lane, wm, wn);
        }
        __syncthreads();   // last gemm done; slots 0..2 all free

        // issue W2 (both chunks, slot 2) — overlaps epilogue-1 STS
        {
            const char* w2c = (const char*)(g_w2t + (size_t)c * HID * HID);
            cpa_tile(sbase + OFF_W2, w2c, HID * 2, tid);
            cpa_tile(sbase + OFF_W2 + 16384u, w2c + (size_t)KC * 2, HID * 2, tid);
            CPA_COMMIT();
        }

        // ========== epilogue 1: relu(acc + b1) -> fp16 h1 (slot 0) ==========
#pragma unroll
        for (int mt = 0; mt < 4; ++mt) {
            int r1 = wm * 64 + mt * 16 + (lane >> 2);
#pragma unroll
            for (int nt = 0; nt < 4; ++nt) {
                int n = wn * 32 + nt * 8 + (lane & 3) * 2;
                uint32_t chb = OFF_H1 + (uint32_t)(n >> 6) * 16384u;
                uint32_t nc = (uint32_t)(n & 63);
                float* cc = acc[mt][nt];
                __half2 h0 = __floats2half2_rn(fmaxf(cc[0] + b1s[n], 0.f),
                                               fmaxf(cc[1] + b1s[n + 1], 0.f));
                __half2 h1v = __floats2half2_rn(fmaxf(cc[2] + b1s[n], 0.f),
                                                fmaxf(cc[3] + b1s[n + 1], 0.f));
                *(__half2*)(smem + chb + SWZ((uint32_t)r1 * 128u + nc * 2u)) = h0;
                *(__half2*)(smem + chb + SWZ((uint32_t)(r1 + 8) * 128u + nc * 2u)) = h1v;
            }
        }
        CPA_WAIT(0);
        __syncthreads();   // h1 + W2 ready

        // ========== GEMM2: h1[128,128] @ W2^T ==========
#pragma unroll
        for (int mt = 0; mt < 4; ++mt)
#pragma unroll
            for (int nt = 0; nt < 4; ++nt)
#pragma unroll
                for (int i = 0; i < 4; ++i) acc[mt][nt][i] = 0.f;

        gemm64(sbase + OFF_H1,           sbase + OFF_W2,           acc, lane, wm, wn);
        gemm64(sbase + OFF_H1 + 16384u,  sbase + OFF_W2 + 16384u,  acc, lane, wm, wn);
        __syncthreads();   // h1/W2 consumption complete; ring free for next channel

        // prefetch next channel's chunks 0,1 — overlaps epilogue-2 math
        if (c < N_C - 1) {
            const char* w1n = (const char*)(g_w1t + (size_t)(c + 1) * HID * DIN);
            cpa_tile(sbase + OFF_STG(0), xg, DIN * 2, tid);
            cpa_tile(sbase + OFF_STG(0) + 16384u, w1n, DIN * 2, tid);
            CPA_COMMIT();
            cpa_tile(sbase + OFF_STG(1), xg + (size_t)KC * 2, DIN * 2, tid);
            cpa_tile(sbase + OFF_STG(1) + 16384u, w1n + (size_t)KC * 2, DIN * 2, tid);
            CPA_COMMIT();
        }

        // ========== epilogue 2: out = relu(acc + b2) . W3 + b3 ==========
#pragma unroll
        for (int mt = 0; mt < 4; ++mt) {
            float p1 = 0.f, p2 = 0.f;
#pragma unroll
            for (int nt = 0; nt < 4; ++nt) {
                int n = wn * 32 + nt * 8 + (lane & 3) * 2;
                float* cc = acc[mt][nt];
                float w0 = w3s[n], w1v = w3s[n + 1];
                float c2a = b2s[n], c2b = b2s[n + 1];
                p1 += fmaxf(cc[0] + c2a, 0.f) * w0 + fmaxf(cc[1] + c2b, 0.f) * w1v;
                p2 += fmaxf(cc[2] + c2a, 0.f) * w0 + fmaxf(cc[3] + c2b, 0.f) * w1v;
            }
            p1 += __shfl_xor_sync(0xFFFFFFFFu, p1, 1);
            p1 += __shfl_xor_sync(0xFFFFFFFFu, p1, 2);
            p2 += __shfl_xor_sync(0xFFFFFFFFu, p2, 1);
            p2 += __shfl_xor_sync(0xFFFFFFFFu, p2, 2);
            if ((lane & 3) == 0) {
                int r = wm * 64 + mt * 16 + (lane >> 2);
                atomicAdd(&rowacc[r], p1);
                atomicAdd(&rowacc[r + 8], p2);
            }
        }
        __syncthreads();
        if (tid < TILE_M)
            out[(size_t)(row0 + tid) * N_C + c] = rowacc[tid] + b3[c];
        __syncthreads();   // protect rowacc/vectors before next channel rewrites
    }
}

// ---------------- launch ----------------
extern "C" void kernel_launch(void* const* d_in, const int* in_sizes, int n_in,
                              void* d_out, int out_size) {
    const float* x  = (const float*)d_in[0];
    const float* W1 = (const float*)d_in[1];
    const float* b1 = (const float*)d_in[2];
    const float* W2 = (const float*)d_in[3];
    const float* b2 = (const float*)d_in[4];
    const float* W3 = (const float*)d_in[5];
    const float* b3 = (const float*)d_in[6];
    float* out = (float*)d_out;

    const int npts = in_sizes[0] / DIN;               // 65536
    const int xblocks = npts * (DIN / 4) / 256;       // 65536
    const int wtot = N_C * DIN * HID + N_C * HID * HID;
    const int wblocks = (wtot + 255) / 256;

    prep_all<<<xblocks + wblocks, 256>>>(x, W1, W2, xblocks);

    cudaFuncSetAttribute(mlp_main, cudaFuncAttributeMaxDynamicSharedMemorySize, SMEM_TOTAL);
    mlp_main<<<npts / TILE_M, 256, SMEM_TOTAL>>>(b1, b2, W3, b3, out);
}

// round 6
// speedup vs baseline: 1.1095x; 1.0723x over previous
#include <cuda_runtime.h>
#include <cuda_fp16.h>
#include <cstdint>

#define N_C    16
#define DIN    1024
#define HID    128
#define TILE_M 128
#define KC     64
#define NCHUNK (DIN / KC)   // 16

// ---------------- device scratch ----------------
__device__ __align__(1024) __half g_xh [67108864];        // 65536*1024 fp16
__device__ __align__(1024) __half g_w1t[N_C * HID * DIN]; // [c][h][d] K-major
__device__ __align__(1024) __half g_w2t[N_C * HID * HID]; // [c][ho][hi] K-major

// ---------------- smem layout ----------------
#define OFF_SA(s)  ((uint32_t)(s) * 16384u)            // 0, 16384
#define OFF_SB(s)  (32768u + (uint32_t)(s) * 16384u)   // 32768, 49152
#define OFF_H1     65536u                              // 32KB: chunk0 @+0, chunk1 @+16384
#define OFF_B1S    98304u
#define OFF_B2S    98816u
#define OFF_W3S    99328u
#define OFF_ACC    99840u
#define SMEM_TOTAL 100352u

#define SWZ(bo) ((bo) ^ (((bo) >> 3) & 0x70))

__device__ __forceinline__ uint32_t smem_u32(const void* p) {
    uint32_t a;
    asm("{ .reg .u64 t; cvta.to.shared.u64 t, %1; cvt.u32.u64 %0, t; }" : "=r"(a) : "l"(p));
    return a;
}

// cp.async a [128 x 128B] tile into swizzled smem; 256 threads, 16B each, 4 iters
__device__ __forceinline__ void cpa_tile(uint32_t soff_abs, const char* g,
                                         int stride_bytes, int tid) {
#pragma unroll
    for (int it = 0; it < 4; ++it) {
        int u = it * 256 + tid;
        int r = u >> 3, w = u & 7;
        uint32_t d = soff_abs + SWZ((uint32_t)(r * 128 + w * 16));
        const char* src = g + (size_t)r * stride_bytes + w * 16;
        asm volatile("cp.async.cg.shared.global [%0], [%1], 16;" :: "r"(d), "l"(src));
    }
}
#define CPA_COMMIT() asm volatile("cp.async.commit_group;" ::: "memory")
#define CPA_WAIT(n)  asm volatile("cp.async.wait_group %0;" :: "n"(n) : "memory")

__device__ __forceinline__ void ldmA(uint32_t addr, uint32_t* f) {
    asm volatile("ldmatrix.sync.aligned.m8n8.x4.shared.b16 {%0,%1,%2,%3}, [%4];"
                 : "=r"(f[0]), "=r"(f[1]), "=r"(f[2]), "=r"(f[3]) : "r"(addr));
}
__device__ __forceinline__ void ldmB4(uint32_t addr, uint32_t* f) {
    asm volatile("ldmatrix.sync.aligned.m8n8.x4.shared.b16 {%0,%1,%2,%3}, [%4];"
                 : "=r"(f[0]), "=r"(f[1]), "=r"(f[2]), "=r"(f[3]) : "r"(addr));
}
__device__ __forceinline__ void mma16816(float* c, const uint32_t* a, const uint32_t* b) {
    asm volatile(
        "mma.sync.aligned.m16n8k16.row.col.f32.f16.f16.f32 "
        "{%0,%1,%2,%3}, {%4,%5,%6,%7}, {%8,%9}, {%0,%1,%2,%3};"
        : "+f"(c[0]), "+f"(c[1]), "+f"(c[2]), "+f"(c[3])
        : "r"(a[0]), "r"(a[1]), "r"(a[2]), "r"(a[3]), "r"(b[0]), "r"(b[1]));
}

__device__ __forceinline__ uint32_t b4_addr(uint32_t sB, int ks, int q, int lane, int wn) {
    int grp = lane >> 3;
    int row = wn * 32 + (2 * q + (grp >> 1)) * 8 + (lane & 7);
    uint32_t bo = (uint32_t)(row * 128 + ks * 32 + ((grp & 1) << 4));
    return sB + SWZ(bo);
}

// one 64-wide K chunk; per-warp ks rotation (swizzle applied to FULL offset)
__device__ __forceinline__ void gemm64(uint32_t sA, uint32_t sB,
                                       float acc[4][4][4], int lane, int wm, int wn,
                                       int rot) {
#pragma unroll
    for (int k2 = 0; k2 < 4; ++k2) {
        int ks = (k2 + rot) & 3;
        uint32_t a[4][4], b[4][2];
#pragma unroll
        for (int mt = 0; mt < 4; ++mt) {
            int row = wm * 64 + mt * 16 + (lane & 15);
            uint32_t bo = (uint32_t)(row * 128 + ks * 32 + ((lane >> 4) << 4));
            ldmA(sA + SWZ(bo), a[mt]);
        }
#pragma unroll
        for (int q = 0; q < 2; ++q)
            ldmB4(b4_addr(sB, ks, q, lane, wn), &b[2 * q][0]);
#pragma unroll
        for (int mt = 0; mt < 4; ++mt)
#pragma unroll
            for (int nt = 0; nt < 4; ++nt)
                mma16816(acc[mt][nt], a[mt], b[nt]);
    }
}

// ---------------- prep kernel (weights only) ----------------
__global__ void prep_w(const float* __restrict__ W1, const float* __restrict__ W2) {
    int i = blockIdx.x * 256 + threadIdx.x;
    const int n1 = N_C * DIN * HID;
    if (i < n1) {
        int c = i / (DIN * HID);
        int rem = i % (DIN * HID);
        int h = rem / DIN;
        int d = rem % DIN;
        g_w1t[i] = __float2half_rn(W1[(c * DIN + d) * HID + h]);
    } else {
        int k = i - n1;
        if (k < N_C * HID * HID) {
            int c = k / (HID * HID);
            int rem = k % (HID * HID);
            int ho = rem / HID;
            int hi = rem % HID;
            g_w2t[k] = __float2half_rn(W2[(c * HID + hi) * HID + ho]);
        }
    }
}

// ---------------- main fused MLP kernel ----------------
__global__ void __launch_bounds__(256, 2) mlp_main(
    const float* __restrict__ xf32,
    const float* __restrict__ b1, const float* __restrict__ b2,
    const float* __restrict__ W3, const float* __restrict__ b3,
    float* __restrict__ out) {
    extern __shared__ char smem[];
    const uint32_t sbase = smem_u32(smem);
    const int tid  = threadIdx.x;
    const int lane = tid & 31;
    const int wid  = tid >> 5;
    const int wm   = wid >> 2;
    const int wn   = wid & 3;
    const int rot  = wid & 3;
    const int row0 = blockIdx.x * TILE_M;

    float* b1s    = (float*)(smem + OFF_B1S);
    float* b2s    = (float*)(smem + OFF_B2S);
    float* w3s    = (float*)(smem + OFF_W3S);
    float* rowacc = (float*)(smem + OFF_ACC);

    // ---- in-kernel x -> fp16 conversion (this CTA's own 128 rows) ----
    {
        const float4* xs = (const float4*)(xf32 + (size_t)row0 * DIN);
        __half2* o = (__half2*)(g_xh + (size_t)row0 * DIN);
#pragma unroll 4
        for (int i = tid; i < TILE_M * DIN / 4; i += 256) {
            float4 v = xs[i];
            o[2 * i]     = __floats2half2_rn(v.x, v.y);
            o[2 * i + 1] = __floats2half2_rn(v.z, v.w);
        }
        __syncthreads();   // CTA-scope order: writes before our cp.async reads
    }

    float acc[4][4][4];
    const char* xg = (const char*)(g_xh + (size_t)row0 * DIN);

    // prologue: channel 0 chunk 0
    {
        cpa_tile(sbase + OFF_SA(0), xg, DIN * 2, tid);
        cpa_tile(sbase + OFF_SB(0), (const char*)g_w1t, DIN * 2, tid);
        CPA_COMMIT();
    }

#pragma unroll 1
    for (int c = 0; c < N_C; ++c) {
        if (tid < HID) {
            b1s[tid] = b1[c * HID + tid];
            b2s[tid] = b2[c * HID + tid];
            w3s[tid] = W3[c * HID + tid];
            rowacc[tid] = 0.f;
        }
#pragma unroll
        for (int mt = 0; mt < 4; ++mt)
#pragma unroll
            for (int nt = 0; nt < 4; ++nt)
#pragma unroll
                for (int i = 0; i < 4; ++i) acc[mt][nt][i] = 0.f;

        const char* w1c = (const char*)(g_w1t + (size_t)c * HID * DIN);

        // ==== GEMM1: round-2 ordering (issue j+1 -> wait -> sync -> gemm -> sync) ====
#pragma unroll 1
        for (int j = 0; j < NCHUNK; ++j) {
            if (j < NCHUNK - 1) {
                int nb = (j + 1) & 1;
                cpa_tile(sbase + OFF_SA(nb), xg + (size_t)(j + 1) * KC * 2, DIN * 2, tid);
                cpa_tile(sbase + OFF_SB(nb), w1c + (size_t)(j + 1) * KC * 2, DIN * 2, tid);
                CPA_COMMIT();
                CPA_WAIT(1);
            } else {
                CPA_WAIT(0);
            }
            __syncthreads();
            gemm64(sbase + OFF_SA(j & 1), sbase + OFF_SB(j & 1), acc, lane, wm, wn, rot);
            __syncthreads();
        }

        // issue W2 (both chunks) into B slots — overlaps epilogue-1 STS
        {
            const char* w2c = (const char*)(g_w2t + (size_t)c * HID * HID);
            cpa_tile(sbase + OFF_SB(0), w2c, HID * 2, tid);
            cpa_tile(sbase + OFF_SB(1), w2c + (size_t)KC * 2, HID * 2, tid);
            CPA_COMMIT();
        }

        // ==== epilogue 1: relu(acc + b1) -> fp16 h1 (own region) ====
#pragma unroll
        for (int mt = 0; mt < 4; ++mt) {
            int r1 = wm * 64 + mt * 16 + (lane >> 2);
#pragma unroll
            for (int nt = 0; nt < 4; ++nt) {
                int n = wn * 32 + nt * 8 + (lane & 3) * 2;
                uint32_t chb = OFF_H1 + (uint32_t)(n >> 6) * 16384u;
                uint32_t nc = (uint32_t)(n & 63);
                float* cc = acc[mt][nt];
                __half2 h0 = __floats2half2_rn(fmaxf(cc[0] + b1s[n], 0.f),
                                               fmaxf(cc[1] + b1s[n + 1], 0.f));
                __half2 h1v = __floats2half2_rn(fmaxf(cc[2] + b1s[n], 0.f),
                                                fmaxf(cc[3] + b1s[n + 1], 0.f));
                *(__half2*)(smem + chb + SWZ((uint32_t)r1 * 128u + nc * 2u)) = h0;
                *(__half2*)(smem + chb + SWZ((uint32_t)(r1 + 8) * 128u + nc * 2u)) = h1v;
            }
        }
        CPA_WAIT(0);
        __syncthreads();   // h1 + W2 ready

        // ==== GEMM2: h1[128,128] @ W2^T ====
#pragma unroll
        for (int mt = 0; mt < 4; ++mt)
#pragma unroll
            for (int nt = 0; nt < 4; ++nt)
#pragma unroll
                for (int i = 0; i < 4; ++i) acc[mt][nt][i] = 0.f;

        gemm64(sbase + OFF_H1,          sbase + OFF_SB(0), acc, lane, wm, wn, rot);
        gemm64(sbase + OFF_H1 + 16384u, sbase + OFF_SB(1), acc, lane, wm, wn, rot);
        __syncthreads();   // slots free

        // prefetch next channel chunk 0 — overlaps epilogue-2 math
        if (c < N_C - 1) {
            const char* w1n = (const char*)(g_w1t + (size_t)(c + 1) * HID * DIN);
            cpa_tile(sbase + OFF_SA(0), xg, DIN * 2, tid);
            cpa_tile(sbase + OFF_SB(0), w1n, DIN * 2, tid);
            CPA_COMMIT();
        }

        // ==== epilogue 2: out = relu(acc + b2) . W3 + b3 ====
#pragma unroll
        for (int mt = 0; mt < 4; ++mt) {
            float p1 = 0.f, p2 = 0.f;
#pragma unroll
            for (int nt = 0; nt < 4; ++nt) {
                int n = wn * 32 + nt * 8 + (lane & 3) * 2;
                float* cc = acc[mt][nt];
                float w0 = w3s[n], w1v = w3s[n + 1];
                float c2a = b2s[n], c2b = b2s[n + 1];
                p1 += fmaxf(cc[0] + c2a, 0.f) * w0 + fmaxf(cc[1] + c2b, 0.f) * w1v;
                p2 += fmaxf(cc[2] + c2a, 0.f) * w0 + fmaxf(cc[3] + c2b, 0.f) * w1v;
            }
            p1 += __shfl_xor_sync(0xFFFFFFFFu, p1, 1);
            p1 += __shfl_xor_sync(0xFFFFFFFFu, p1, 2);
            p2 += __shfl_xor_sync(0xFFFFFFFFu, p2, 1);
            p2 += __shfl_xor_sync(0xFFFFFFFFu, p2, 2);
            if ((lane & 3) == 0) {
                int r = wm * 64 + mt * 16 + (lane >> 2);
                atomicAdd(&rowacc[r], p1);
                atomicAdd(&rowacc[r + 8], p2);
            }
        }
        __syncthreads();
        if (tid < TILE_M)
            out[(size_t)(row0 + tid) * N_C + c] = rowacc[tid] + b3[c];
        __syncthreads();   // protect smem vectors before next channel rewrites
    }
}

// ---------------- launch ----------------
extern "C" void kernel_launch(void* const* d_in, const int* in_sizes, int n_in,
                              void* d_out, int out_size) {
    const float* x  = (const float*)d_in[0];
    const float* W1 = (const float*)d_in[1];
    const float* b1 = (const float*)d_in[2];
    const float* W2 = (const float*)d_in[3];
    const float* b2 = (const float*)d_in[4];
    const float* W3 = (const float*)d_in[5];
    const float* b3 = (const float*)d_in[6];
    float* out = (float*)d_out;

    const int npts = in_sizes[0] / DIN;               // 65536
    const int wtot = N_C * DIN * HID + N_C * HID * HID;
    prep_w<<<(wtot + 255) / 256, 256>>>(W1, W2);

    cudaFuncSetAttribute(mlp_main, cudaFuncAttributeMaxDynamicSharedMemorySize, SMEM_TOTAL);
    mlp_main<<<npts / TILE_M, 256, SMEM_TOTAL>>>(x, b1, b2, W3, b3, out);
}